// round 3
// baseline (speedup 1.0000x reference)
#include <cuda_runtime.h>
#include <cstdint>

#define BB   2
#define NN   16384
#define SS   4096
#define KK   32
#define FIN  16
#define MTOT (BB*SS)      /* 8192 centers */
#define BN   (BB*NN)      /* 32768 points */
#define NCELL 1000        /* 10x10x10 cells of size R=0.1 per cloud */
#define R2   0.01f

// ---------------- device scratch (no runtime allocation allowed) ----------------
__device__ float g_posx[BN], g_posy[BN], g_posz[BN];
__device__ int   g_sidx[MTOT];                 // selected local point idx per (b,s)
__device__ float g_cx[MTOT], g_cy[MTOT], g_cz[MTOT];
__device__ int   g_cellCnt[BB*NCELL];
__device__ int   g_cellStart[BB*NCELL];
__device__ int   g_cellCur[BB*NCELL];
__device__ int   g_cellPts[BN];
__device__ float g_xw[BN*64];                  // x @ W1[:16] + b1   (8 MB)
__device__ int   g_nbr[MTOT*KK];
__device__ int   g_cnt[MTOT];

// ---------------- prep: SoA split of pos + zero cell counts ----------------
__global__ void prep_kernel(const float* __restrict__ pos) {
    int i = blockIdx.x * blockDim.x + threadIdx.x;
    if (i < BN) {
        g_posx[i] = pos[3*i+0];
        g_posy[i] = pos[3*i+1];
        g_posz[i] = pos[3*i+2];
    }
    if (i < BB*NCELL) g_cellCnt[i] = 0;
}

__device__ __forceinline__ int cell_of(float px, float py, float pz, int b) {
    int cx = (int)(px * 10.0f); cx = cx < 0 ? 0 : (cx > 9 ? 9 : cx);
    int cy = (int)(py * 10.0f); cy = cy < 0 ? 0 : (cy > 9 ? 9 : cy);
    int cz = (int)(pz * 10.0f); cz = cz < 0 ? 0 : (cz > 9 ? 9 : cz);
    return b * NCELL + (cz * 10 + cy) * 10 + cx;
}

__global__ void count_kernel() {
    int i = blockIdx.x * blockDim.x + threadIdx.x;
    if (i >= BN) return;
    int b = i >> 14;
    atomicAdd(&g_cellCnt[cell_of(g_posx[i], g_posy[i], g_posz[i], b)], 1);
}

// single-warp exclusive scan over 2000 cells
__global__ void scan_kernel() {
    int lane = threadIdx.x;
    int acc = 0;
    for (int base = 0; base < BB*NCELL; base += 32) {
        int idx = base + lane;
        int v = (idx < BB*NCELL) ? g_cellCnt[idx] : 0;
        int inc = v;
        #pragma unroll
        for (int o = 1; o < 32; o <<= 1) {
            int n = __shfl_up_sync(0xffffffffu, inc, o);
            if (lane >= o) inc += n;
        }
        if (idx < BB*NCELL) {
            g_cellStart[idx] = acc + inc - v;
            g_cellCur[idx]   = acc + inc - v;
        }
        acc += __shfl_sync(0xffffffffu, inc, 31);
    }
}

__global__ void scatter_kernel() {
    int i = blockIdx.x * blockDim.x + threadIdx.x;
    if (i >= BN) return;
    int b = i >> 14;
    int cid = cell_of(g_posx[i], g_posy[i], g_posz[i], b);
    int slot = atomicAdd(&g_cellCur[cid], 1);
    g_cellPts[slot] = i & (NN - 1);   // local index within cloud
}

// ---------------- FPS: one block per cloud, pos in smem, dmin in regs ----------------
#define FPS_SMEM (3*NN*4 + 32*4 + 32*4 + 16)

__global__ void __launch_bounds__(1024, 1) fps_kernel() {
    extern __shared__ float sm[];
    float* sx = sm;
    float* sy = sm + NN;
    float* sz = sm + 2*NN;
    float* rv = sm + 3*NN;          // 32 warp bests
    int*   ri = (int*)(rv + 32);    // 32 warp best indices
    int*   slast = ri + 32;

    const int b = blockIdx.x;
    const int tid = threadIdx.x;

    for (int i = tid; i < NN; i += 1024) {
        sx[i] = g_posx[b*NN + i];
        sy[i] = g_posy[b*NN + i];
        sz[i] = g_posz[b*NN + i];
    }
    float dmin[16];
    #pragma unroll
    for (int u = 0; u < 16; u++) dmin[u] = 1e10f;
    if (tid == 0) g_sidx[b*SS] = 0;
    __syncthreads();

    int last = 0;
    for (int t = 1; t < SS; t++) {
        const float lx = sx[last], ly = sy[last], lz = sz[last];
        float bv = -1.0f; int bi = 0;
        #pragma unroll
        for (int u = 0; u < 8; u++) {
            int i = 2*tid + u*2048;
            float2 px = *(const float2*)(sx + i);
            float2 py = *(const float2*)(sy + i);
            float2 pz = *(const float2*)(sz + i);
            // first of pair
            {
                float dx = px.x - lx, dy = py.x - ly, dz = pz.x - lz;
                float d = fmaf(dz, dz, fmaf(dy, dy, dx*dx));
                float dm = fminf(dmin[2*u], d);
                dmin[2*u] = dm;
                if (dm > bv) { bv = dm; bi = i; }
            }
            // second of pair
            {
                float dx = px.y - lx, dy = py.y - ly, dz = pz.y - lz;
                float d = fmaf(dz, dz, fmaf(dy, dy, dx*dx));
                float dm = fminf(dmin[2*u+1], d);
                dmin[2*u+1] = dm;
                if (dm > bv) { bv = dm; bi = i + 1; }
            }
        }
        // warp argmax (value desc, index asc tiebreak => first occurrence)
        #pragma unroll
        for (int o = 16; o; o >>= 1) {
            float ov = __shfl_down_sync(0xffffffffu, bv, o);
            int   oi = __shfl_down_sync(0xffffffffu, bi, o);
            if (ov > bv || (ov == bv && oi < bi)) { bv = ov; bi = oi; }
        }
        int wid = tid >> 5;
        if ((tid & 31) == 0) { rv[wid] = bv; ri[wid] = bi; }
        __syncthreads();
        if (tid < 32) {
            bv = rv[tid]; bi = ri[tid];
            #pragma unroll
            for (int o = 16; o; o >>= 1) {
                float ov = __shfl_down_sync(0xffffffffu, bv, o);
                int   oi = __shfl_down_sync(0xffffffffu, bi, o);
                if (ov > bv || (ov == bv && oi < bi)) { bv = ov; bi = oi; }
            }
            if (tid == 0) { g_sidx[b*SS + t] = bi; *slast = bi; }
        }
        __syncthreads();
        last = *slast;
    }
}

// ---------------- centers + batch outputs ----------------
__global__ void centers_kernel(float* out_c, float* out_b) {
    int i = blockIdx.x * blockDim.x + threadIdx.x;
    if (i >= MTOT) return;
    int b = i >> 12;
    int gp = b*NN + g_sidx[i];
    float cx = g_posx[gp], cy = g_posy[gp], cz = g_posz[gp];
    g_cx[i] = cx; g_cy[i] = cy; g_cz[i] = cz;
    if (out_c) { out_c[3*i+0] = cx; out_c[3*i+1] = cy; out_c[3*i+2] = cz; }
    if (out_b) { out_b[i] = (float)b; }
}

// ---------------- xw precompute: x @ W1[:16] + b1 ----------------
__global__ void xw_kernel(const float* __restrict__ x,
                          const float* __restrict__ W1,
                          const float* __restrict__ b1) {
    int gid = blockIdx.x * blockDim.x + threadIdx.x;
    if (gid >= BN * 16) return;
    int j  = gid >> 4;
    int c4 = (gid & 15) * 4;
    float a0 = b1[c4+0], a1 = b1[c4+1], a2 = b1[c4+2], a3 = b1[c4+3];
    const float* xr = x + j * FIN;
    #pragma unroll
    for (int k = 0; k < FIN; k++) {
        float xv = xr[k];
        const float* w = W1 + k*64 + c4;
        a0 = fmaf(xv, w[0], a0);
        a1 = fmaf(xv, w[1], a1);
        a2 = fmaf(xv, w[2], a2);
        a3 = fmaf(xv, w[3], a3);
    }
    float4* dst = (float4*)(g_xw + j*64 + c4);
    *dst = make_float4(a0, a1, a2, a3);
}

// ---------------- ball query: warp per center, grid cells, K smallest indices ----------------
__global__ void __launch_bounds__(256) ballq_kernel() {
    __shared__ int cand[8][256];
    __shared__ int scnt[8];
    int wid = threadIdx.x >> 5, lane = threadIdx.x & 31;
    int i = blockIdx.x * 8 + wid;
    int b = i >> 12, s = i & 4095;
    float cx = g_cx[i], cy = g_cy[i], cz = g_cz[i];
    if (lane == 0) scnt[wid] = 0;
    __syncwarp();

    int icx = (int)(cx * 10.0f); icx = icx < 0 ? 0 : (icx > 9 ? 9 : icx);
    int icy = (int)(cy * 10.0f); icy = icy < 0 ? 0 : (icy > 9 ? 9 : icy);
    int icz = (int)(cz * 10.0f); icz = icz < 0 ? 0 : (icz > 9 ? 9 : icz);
    int zlo = icz > 0 ? icz-1 : 0, zhi = icz < 9 ? icz+1 : 9;
    int ylo = icy > 0 ? icy-1 : 0, yhi = icy < 9 ? icy+1 : 9;
    int xlo = icx > 0 ? icx-1 : 0, xhi = icx < 9 ? icx+1 : 9;

    for (int zz = zlo; zz <= zhi; zz++)
    for (int yy = ylo; yy <= yhi; yy++)
    for (int xx = xlo; xx <= xhi; xx++) {
        int cid = b*NCELL + (zz*10 + yy)*10 + xx;
        int st = g_cellStart[cid];
        int en = st + g_cellCnt[cid];
        for (int idx = st + lane; idx < en; idx += 32) {
            int pid = g_cellPts[idx];
            int gp = b*NN + pid;
            float dx = g_posx[gp] - cx, dy = g_posy[gp] - cy, dz = g_posz[gp] - cz;
            float d2 = fmaf(dz, dz, fmaf(dy, dy, dx*dx));
            bool ok = (d2 <= R2) && !(b == 0 && pid == s);  // PyG remove_self_loops
            if (ok) {
                int p = atomicAdd(&scnt[wid], 1);
                if (p < 256) cand[wid][p] = pid;
            }
        }
    }
    __syncwarp();
    int m = scnt[wid]; if (m > 256) m = 256;
    int take = m < KK ? m : KK;
    // extract 'take' smallest indices (index order = reference sort order)
    for (int r = 0; r < take; r++) {
        int bestkey = 0x7FFFFFFF;
        for (int j = lane; j < m; j += 32) {
            int v = cand[wid][j];          // removed entries hold 0x7FFF (> any pid)
            int key = (v << 8) | j;
            bestkey = min(bestkey, key);
        }
        #pragma unroll
        for (int o = 16; o; o >>= 1)
            bestkey = min(bestkey, __shfl_down_sync(0xffffffffu, bestkey, o));
        bestkey = __shfl_sync(0xffffffffu, bestkey, 0);
        if (lane == 0) {
            g_nbr[i*KK + r] = bestkey >> 8;
            cand[wid][bestkey & 255] = 0x7FFF;
        }
        __syncwarp();
    }
    if (lane == 0) g_cnt[i] = take;
}

// ---------------- fused MLP + max-pool: warp per center ----------------
#define MLP_SMEM ((4096 + 8192 + 192 + 64 + 128) * 4)

__global__ void __launch_bounds__(256) mlp_kernel(const float* __restrict__ W1,
                                                  const float* __restrict__ W2,
                                                  const float* __restrict__ b2,
                                                  const float* __restrict__ W3,
                                                  const float* __restrict__ b3,
                                                  float* __restrict__ out_x) {
    extern __shared__ float sm[];
    float* W2s  = sm;            // 64x64
    float* W3s  = W2s + 4096;    // 64x128
    float* W1rs = W3s + 8192;    // rows 16..18 of W1 (rel weights), 3x64
    float* b2s  = W1rs + 192;
    float* b3s  = b2s + 64;
    int tid = threadIdx.x;
    for (int k = tid; k < 4096; k += 256) W2s[k] = W2[k];
    for (int k = tid; k < 8192; k += 256) W3s[k] = W3[k];
    if (tid < 192) W1rs[tid] = W1[FIN*64 + tid];
    if (tid < 64)  b2s[tid] = b2[tid];
    if (tid < 128) b3s[tid] = b3[tid];
    __syncthreads();

    int wid = tid >> 5, lane = tid & 31;
    int i = blockIdx.x * 8 + wid;
    int b = i >> 12;
    int cnt = g_cnt[i];
    float cx = g_cx[i], cy = g_cy[i], cz = g_cz[i];

    // hoisted per-lane weights (lane owns h1/h2 channels 2*lane, 2*lane+1; h3 channels 4*lane..+3)
    float2 w1x = ((const float2*)(W1rs +   0))[lane];
    float2 w1y = ((const float2*)(W1rs +  64))[lane];
    float2 w1z = ((const float2*)(W1rs + 128))[lane];
    float2 bb2 = ((const float2*)b2s)[lane];
    float4 bb3 = ((const float4*)b3s)[lane];

    float m0 = -1e30f, m1 = -1e30f, m2 = -1e30f, m3 = -1e30f;

    for (int e = 0; e <= cnt; e++) {
        // e == cnt -> PyG add_self_loops edge: src flat index == global dst id == i
        int j = (e < cnt) ? (b*NN + g_nbr[i*KK + e]) : i;
        float rx = g_posx[j] - cx, ry = g_posy[j] - cy, rz = g_posz[j] - cz;
        float2 xw = ((const float2*)(g_xw + j*64))[lane];
        float h1a = fmaf(rz, w1z.x, fmaf(ry, w1y.x, fmaf(rx, w1x.x, xw.x)));
        float h1b = fmaf(rz, w1z.y, fmaf(ry, w1y.y, fmaf(rx, w1x.y, xw.y)));
        h1a = fmaxf(h1a, 0.0f);
        h1b = fmaxf(h1b, 0.0f);

        float a0 = bb2.x, a1 = bb2.y;
        #pragma unroll 8
        for (int k0 = 0; k0 < 32; k0++) {
            float va = __shfl_sync(0xffffffffu, h1a, k0);   // h1[2*k0]
            float vb = __shfl_sync(0xffffffffu, h1b, k0);   // h1[2*k0+1]
            float2 wa = ((const float2*)(W2s + (2*k0  )*64))[lane];
            float2 wb = ((const float2*)(W2s + (2*k0+1)*64))[lane];
            a0 = fmaf(va, wa.x, a0); a0 = fmaf(vb, wb.x, a0);
            a1 = fmaf(va, wa.y, a1); a1 = fmaf(vb, wb.y, a1);
        }
        float h2a = fmaxf(a0, 0.0f), h2b = fmaxf(a1, 0.0f);

        float c0 = bb3.x, c1 = bb3.y, c2 = bb3.z, c3 = bb3.w;
        #pragma unroll 8
        for (int k0 = 0; k0 < 32; k0++) {
            float va = __shfl_sync(0xffffffffu, h2a, k0);   // h2[2*k0]
            float vb = __shfl_sync(0xffffffffu, h2b, k0);   // h2[2*k0+1]
            float4 wa = ((const float4*)(W3s + (2*k0  )*128))[lane];
            float4 wb = ((const float4*)(W3s + (2*k0+1)*128))[lane];
            c0 = fmaf(va, wa.x, c0); c0 = fmaf(vb, wb.x, c0);
            c1 = fmaf(va, wa.y, c1); c1 = fmaf(vb, wb.y, c1);
            c2 = fmaf(va, wa.z, c2); c2 = fmaf(vb, wb.z, c2);
            c3 = fmaf(va, wa.w, c3); c3 = fmaf(vb, wb.w, c3);
        }
        m0 = fmaxf(m0, c0); m1 = fmaxf(m1, c1);
        m2 = fmaxf(m2, c2); m3 = fmaxf(m3, c3);
    }
    ((float4*)(out_x + i*128))[lane] = make_float4(m0, m1, m2, m3);
}

// ---------------- host launcher ----------------
extern "C" void kernel_launch(void* const* d_in, const int* in_sizes, int n_in,
                              void* d_out, int out_size) {
    const float* x   = (const float*)d_in[0];
    const float* pos = (const float*)d_in[1];
    // d_in[2] = batch (int32) -- derivable, unused
    const float* W1  = (const float*)d_in[3];
    const float* b1  = (const float*)d_in[4];
    const float* W2  = (const float*)d_in[5];
    const float* b2  = (const float*)d_in[6];
    const float* W3  = (const float*)d_in[7];
    const float* b3  = (const float*)d_in[8];

    float* out   = (float*)d_out;
    float* out_c = (out_size >= MTOT*131) ? out + MTOT*128 : nullptr;
    float* out_b = (out_size >= MTOT*132) ? out + MTOT*131 : nullptr;

    cudaFuncSetAttribute(fps_kernel, cudaFuncAttributeMaxDynamicSharedMemorySize, FPS_SMEM);
    cudaFuncSetAttribute(mlp_kernel, cudaFuncAttributeMaxDynamicSharedMemorySize, MLP_SMEM);

    prep_kernel   <<<(BN + 255)/256, 256>>>(pos);
    count_kernel  <<<(BN + 255)/256, 256>>>();
    scan_kernel   <<<1, 32>>>();
    scatter_kernel<<<(BN + 255)/256, 256>>>();
    xw_kernel     <<<(BN*16 + 127)/128, 128>>>(x, W1, b1);
    fps_kernel    <<<BB, 1024, FPS_SMEM>>>();
    centers_kernel<<<(MTOT + 255)/256, 256>>>(out_c, out_b);
    ballq_kernel  <<<MTOT/8, 256>>>();
    mlp_kernel    <<<MTOT/8, 256, MLP_SMEM>>>(W1, W2, b2, W3, b3, out);
}

// round 5
// speedup vs baseline: 1.0910x; 1.0910x over previous
#include <cuda_runtime.h>
#include <cstdint>

#define BB   2
#define NN   16384
#define SS   4096
#define KK   32
#define FIN  16
#define MTOT (BB*SS)      /* 8192 centers */
#define BN   (BB*NN)      /* 32768 points */
#define NCELL 1000        /* 10x10x10 cells of size R=0.1 per cloud */
#define R2   0.01f

// ---------------- device scratch (no runtime allocation allowed) ----------------
__device__ float g_posx[BN], g_posy[BN], g_posz[BN];
__device__ int   g_sidx[MTOT];                 // selected local point idx per (b,s)
__device__ float g_cx[MTOT], g_cy[MTOT], g_cz[MTOT];
__device__ int   g_cellCnt[BB*NCELL];
__device__ int   g_cellStart[BB*NCELL];
__device__ int   g_cellCur[BB*NCELL];
__device__ int   g_cellPts[BN];
__device__ float g_opx[BN], g_opy[BN], g_opz[BN];  // cell-ordered positions
__device__ int   g_opid[BN];                        // cell-ordered -> local point id
__device__ int2  g_ozp[BN];                         // fused {z bits, local pid}
__device__ float g_xw[BN*64];                  // x @ W1[:16] + b1   (8 MB)
__device__ int   g_nbr[MTOT*KK];
__device__ int   g_cnt[MTOT];

// ---------------- prep: SoA split of pos + zero cell counts ----------------
__global__ void prep_kernel(const float* __restrict__ pos) {
    int i = blockIdx.x * blockDim.x + threadIdx.x;
    if (i < BN) {
        g_posx[i] = pos[3*i+0];
        g_posy[i] = pos[3*i+1];
        g_posz[i] = pos[3*i+2];
    }
    if (i < BB*NCELL) g_cellCnt[i] = 0;
}

__device__ __forceinline__ int cell_of(float px, float py, float pz, int b) {
    int cx = (int)(px * 10.0f); cx = cx < 0 ? 0 : (cx > 9 ? 9 : cx);
    int cy = (int)(py * 10.0f); cy = cy < 0 ? 0 : (cy > 9 ? 9 : cy);
    int cz = (int)(pz * 10.0f); cz = cz < 0 ? 0 : (cz > 9 ? 9 : cz);
    return b * NCELL + (cz * 10 + cy) * 10 + cx;
}

__global__ void count_kernel() {
    int i = blockIdx.x * blockDim.x + threadIdx.x;
    if (i >= BN) return;
    int b = i >> 14;
    atomicAdd(&g_cellCnt[cell_of(g_posx[i], g_posy[i], g_posz[i], b)], 1);
}

// single-warp exclusive scan over 2000 cells
__global__ void scan_kernel() {
    int lane = threadIdx.x;
    int acc = 0;
    for (int base = 0; base < BB*NCELL; base += 32) {
        int idx = base + lane;
        int v = (idx < BB*NCELL) ? g_cellCnt[idx] : 0;
        int inc = v;
        #pragma unroll
        for (int o = 1; o < 32; o <<= 1) {
            int n = __shfl_up_sync(0xffffffffu, inc, o);
            if (lane >= o) inc += n;
        }
        if (idx < BB*NCELL) {
            g_cellStart[idx] = acc + inc - v;
            g_cellCur[idx]   = acc + inc - v;
        }
        acc += __shfl_sync(0xffffffffu, inc, 31);
    }
}

__global__ void scatter_kernel() {
    int i = blockIdx.x * blockDim.x + threadIdx.x;
    if (i >= BN) return;
    int b = i >> 14;
    int cid = cell_of(g_posx[i], g_posy[i], g_posz[i], b);
    int slot = atomicAdd(&g_cellCur[cid], 1);
    g_cellPts[slot] = i & (NN - 1);   // local index within cloud
}

// build cell-ordered SoA position arrays + id map
__global__ void gather_kernel() {
    int i = blockIdx.x * blockDim.x + threadIdx.x;
    if (i >= BN) return;
    int b = i >> 14;                 // slots of cloud b occupy [b*NN, (b+1)*NN)
    int pid = g_cellPts[i];
    int gp = b*NN + pid;
    float z = g_posz[gp];
    g_opx[i] = g_posx[gp];
    g_opy[i] = g_posy[gp];
    g_opz[i] = z;
    g_opid[i] = pid;
    g_ozp[i] = make_int2(__float_as_int(z), pid);
}

// ---------------- grid-pruned FPS with exact argmax ordering ----------------
// key = (bits(dmin) << 32) | (0xFFFFFFFF - pid): max key == (max dmin, min pid)
__device__ __forceinline__ unsigned long long fps_key(float v, int pid) {
    return ((unsigned long long)__float_as_uint(v) << 32)
         | (unsigned long long)(0xFFFFFFFFu - (unsigned)pid);
}

#define FPS2_SMEM (3*NN*4 + NCELL*8 + 32*8 + NCELL*4 + NCELL*4 + 1024*4 + 64)

__global__ void __launch_bounds__(1024, 1) fps_grid_kernel() {
    extern __shared__ float sm[];
    float* sx    = sm;                               // NN
    float* sy    = sx + NN;                          // NN
    float* sdmin = sy + NN;                          // NN
    unsigned long long* skey = (unsigned long long*)(sdmin + NN);  // NCELL (8B aligned)
    unsigned long long* spk  = skey + NCELL;         // 32 warp partials
    int*   sstart= (int*)(spk + 32);                 // NCELL
    int*   scnt  = sstart + NCELL;                   // NCELL
    int*   swl   = scnt + NCELL;                     // 1024 worklist
    int*   swlcnt= swl + 1024;                       // 1
    float* slast = (float*)(swlcnt + 1);             // 3

    const int b    = blockIdx.x;
    const int tid  = threadIdx.x;
    const int lane = tid & 31;
    const int wid  = tid >> 5;
    const int gbase = b * NN;

    for (int i = tid; i < NN; i += 1024) {
        sx[i] = g_opx[gbase + i];
        sy[i] = g_opy[gbase + i];
        sdmin[i] = 1e10f;
    }
    for (int c = tid; c < NCELL; c += 1024) {
        int cn = g_cellCnt[b*NCELL + c];
        sstart[c] = g_cellStart[b*NCELL + c] - gbase;
        scnt[c]   = cn;
        skey[c]   = cn ? fps_key(1e10f, 0) : 0ull;
    }
    if (tid == 0) {
        g_sidx[b*SS] = 0;
        slast[0] = g_posx[gbase];   // original point 0 of this cloud
        slast[1] = g_posy[gbase];
        slast[2] = g_posz[gbase];
        *swlcnt = 0;
    }
    __syncthreads();

    for (int t = 1; t < SS; t++) {
        const float lx = slast[0], ly = slast[1], lz = slast[2];

        // ---- phase A: per-cell lower-bound prune + worklist compaction ----
        bool need = false;
        if (tid < NCELL) {
            int cz = tid / 100;
            int r  = tid - cz * 100;
            int cy = r / 10;
            int cx = r - cy * 10;
            float ex = fmaxf(fmaxf((float)cx * 0.1f - lx, lx - (float)(cx+1) * 0.1f), 0.0f);
            float ey = fmaxf(fmaxf((float)cy * 0.1f - ly, ly - (float)(cy+1) * 0.1f), 0.0f);
            float ez = fmaxf(fmaxf((float)cz * 0.1f - lz, lz - (float)(cz+1) * 0.1f), 0.0f);
            float lb2 = fmaf(ez, ez, fmaf(ey, ey, ex*ex));
            float gv = __uint_as_float((unsigned)(skey[tid] >> 32));
            need = (lb2 * 0.9998f < gv);   // margin: never wrongly skip
        }
        unsigned m = __ballot_sync(0xffffffffu, need);
        if (m) {
            int cntw = __popc(m);
            int leader = __ffs(m) - 1;
            int base = 0;
            if (lane == leader) base = atomicAdd(swlcnt, cntw);
            base = __shfl_sync(0xffffffffu, base, leader);
            if (need) swl[base + __popc(m & ((1u << lane) - 1u))] = tid;
        }
        __syncthreads();
        const int W = *swlcnt;

        // ---- phase B: warp per touched cell, update dmin + keyed cell argmax ----
        for (int wi = wid; wi < W; wi += 32) {
            int c  = swl[wi];
            int st = sstart[c], cn = scnt[c];
            unsigned long long bk = 0ull;
            for (int p = lane; p < cn; p += 32) {
                int s = st + p;
                int2 zp = g_ozp[gbase + s];
                float dx = sx[s] - lx;
                float dy = sy[s] - ly;
                float dz = __int_as_float(zp.x) - lz;
                float d  = fmaf(dz, dz, fmaf(dy, dy, dx*dx));
                float nm = fminf(sdmin[s], d);
                sdmin[s] = nm;
                unsigned long long k = fps_key(nm, zp.y);
                bk = (k > bk) ? k : bk;
            }
            #pragma unroll
            for (int o = 16; o; o >>= 1) {
                unsigned long long ok = __shfl_down_sync(0xffffffffu, bk, o);
                bk = (ok > bk) ? ok : bk;
            }
            if (lane == 0) skey[c] = bk;
        }
        __syncthreads();

        // ---- phase C: global keyed argmax over cells ----
        unsigned long long bk = (tid < NCELL) ? skey[tid] : 0ull;
        #pragma unroll
        for (int o = 16; o; o >>= 1) {
            unsigned long long ok = __shfl_down_sync(0xffffffffu, bk, o);
            bk = (ok > bk) ? ok : bk;
        }
        if (lane == 0) spk[wid] = bk;
        __syncthreads();
        if (wid == 0) {
            bk = spk[lane];
            #pragma unroll
            for (int o = 16; o; o >>= 1) {
                unsigned long long ok = __shfl_down_sync(0xffffffffu, bk, o);
                bk = (ok > bk) ? ok : bk;
            }
            if (lane == 0) {
                int pid = (int)(0xFFFFFFFFu - (unsigned)(bk & 0xFFFFFFFFull));
                g_sidx[b*SS + t] = pid;
                slast[0] = g_posx[gbase + pid];
                slast[1] = g_posy[gbase + pid];
                slast[2] = g_posz[gbase + pid];
            }
            if (lane == 1) *swlcnt = 0;
        }
        __syncthreads();
    }
}

// ---------------- centers + batch outputs ----------------
__global__ void centers_kernel(float* out_c, float* out_b) {
    int i = blockIdx.x * blockDim.x + threadIdx.x;
    if (i >= MTOT) return;
    int b = i >> 12;
    int gp = b*NN + g_sidx[i];
    float cx = g_posx[gp], cy = g_posy[gp], cz = g_posz[gp];
    g_cx[i] = cx; g_cy[i] = cy; g_cz[i] = cz;
    if (out_c) { out_c[3*i+0] = cx; out_c[3*i+1] = cy; out_c[3*i+2] = cz; }
    if (out_b) { out_b[i] = (float)b; }
}

// ---------------- xw precompute: x @ W1[:16] + b1 ----------------
__global__ void xw_kernel(const float* __restrict__ x,
                          const float* __restrict__ W1,
                          const float* __restrict__ b1) {
    int gid = blockIdx.x * blockDim.x + threadIdx.x;
    if (gid >= BN * 16) return;
    int j  = gid >> 4;
    int c4 = (gid & 15) * 4;
    float a0 = b1[c4+0], a1 = b1[c4+1], a2 = b1[c4+2], a3 = b1[c4+3];
    const float* xr = x + j * FIN;
    #pragma unroll
    for (int k = 0; k < FIN; k++) {
        float xv = xr[k];
        const float* w = W1 + k*64 + c4;
        a0 = fmaf(xv, w[0], a0);
        a1 = fmaf(xv, w[1], a1);
        a2 = fmaf(xv, w[2], a2);
        a3 = fmaf(xv, w[3], a3);
    }
    float4* dst = (float4*)(g_xw + j*64 + c4);
    *dst = make_float4(a0, a1, a2, a3);
}

// ---------------- ball query: warp per center, grid cells, K smallest indices ----------------
__global__ void __launch_bounds__(256) ballq_kernel() {
    __shared__ int cand[8][256];
    __shared__ int scnt_s[8];
    int wid = threadIdx.x >> 5, lane = threadIdx.x & 31;
    int i = blockIdx.x * 8 + wid;
    int b = i >> 12, s = i & 4095;
    float cx = g_cx[i], cy = g_cy[i], cz = g_cz[i];
    if (lane == 0) scnt_s[wid] = 0;
    __syncwarp();

    int icx = (int)(cx * 10.0f); icx = icx < 0 ? 0 : (icx > 9 ? 9 : icx);
    int icy = (int)(cy * 10.0f); icy = icy < 0 ? 0 : (icy > 9 ? 9 : icy);
    int icz = (int)(cz * 10.0f); icz = icz < 0 ? 0 : (icz > 9 ? 9 : icz);
    int zlo = icz > 0 ? icz-1 : 0, zhi = icz < 9 ? icz+1 : 9;
    int ylo = icy > 0 ? icy-1 : 0, yhi = icy < 9 ? icy+1 : 9;
    int xlo = icx > 0 ? icx-1 : 0, xhi = icx < 9 ? icx+1 : 9;

    for (int zz = zlo; zz <= zhi; zz++)
    for (int yy = ylo; yy <= yhi; yy++)
    for (int xx = xlo; xx <= xhi; xx++) {
        int cid = b*NCELL + (zz*10 + yy)*10 + xx;
        int st = g_cellStart[cid];
        int en = st + g_cellCnt[cid];
        for (int idx = st + lane; idx < en; idx += 32) {
            float dx = g_opx[idx] - cx, dy = g_opy[idx] - cy, dz = g_opz[idx] - cz;
            float d2 = fmaf(dz, dz, fmaf(dy, dy, dx*dx));
            int pid = g_opid[idx];
            bool ok = (d2 <= R2) && !(b == 0 && pid == s);  // PyG remove_self_loops
            if (ok) {
                int p = atomicAdd(&scnt_s[wid], 1);
                if (p < 256) cand[wid][p] = pid;
            }
        }
    }
    __syncwarp();
    int m = scnt_s[wid]; if (m > 256) m = 256;
    int take = m < KK ? m : KK;
    // extract 'take' smallest indices (index order = reference sort order)
    for (int r = 0; r < take; r++) {
        int bestkey = 0x7FFFFFFF;
        for (int j = lane; j < m; j += 32) {
            int v = cand[wid][j];          // removed entries hold 0x7FFF (> any pid)
            int key = (v << 8) | j;
            bestkey = min(bestkey, key);
        }
        #pragma unroll
        for (int o = 16; o; o >>= 1)
            bestkey = min(bestkey, __shfl_down_sync(0xffffffffu, bestkey, o));
        bestkey = __shfl_sync(0xffffffffu, bestkey, 0);
        if (lane == 0) {
            g_nbr[i*KK + r] = bestkey >> 8;
            cand[wid][bestkey & 255] = 0x7FFF;
        }
        __syncwarp();
    }
    if (lane == 0) g_cnt[i] = take;
}

// ---------------- fused MLP + max-pool: warp per center ----------------
#define MLP_SMEM ((4096 + 8192 + 192 + 64 + 128) * 4)

__global__ void __launch_bounds__(256) mlp_kernel(const float* __restrict__ W1,
                                                  const float* __restrict__ W2,
                                                  const float* __restrict__ b2,
                                                  const float* __restrict__ W3,
                                                  const float* __restrict__ b3,
                                                  float* __restrict__ out_x) {
    extern __shared__ float sm[];
    float* W2s  = sm;            // 64x64
    float* W3s  = W2s + 4096;    // 64x128
    float* W1rs = W3s + 8192;    // rows 16..18 of W1 (rel weights), 3x64
    float* b2s  = W1rs + 192;
    float* b3s  = b2s + 64;
    int tid = threadIdx.x;
    for (int k = tid; k < 4096; k += 256) W2s[k] = W2[k];
    for (int k = tid; k < 8192; k += 256) W3s[k] = W3[k];
    if (tid < 192) W1rs[tid] = W1[FIN*64 + tid];
    if (tid < 64)  b2s[tid] = b2[tid];
    if (tid < 128) b3s[tid] = b3[tid];
    __syncthreads();

    int wid = tid >> 5, lane = tid & 31;
    int i = blockIdx.x * 8 + wid;
    int b = i >> 12;
    int cnt = g_cnt[i];
    float cx = g_cx[i], cy = g_cy[i], cz = g_cz[i];

    float2 w1x = ((const float2*)(W1rs +   0))[lane];
    float2 w1y = ((const float2*)(W1rs +  64))[lane];
    float2 w1z = ((const float2*)(W1rs + 128))[lane];
    float2 bb2 = ((const float2*)b2s)[lane];
    float4 bb3 = ((const float4*)b3s)[lane];

    float m0 = -1e30f, m1 = -1e30f, m2 = -1e30f, m3 = -1e30f;

    for (int e = 0; e <= cnt; e++) {
        // e == cnt -> PyG add_self_loops edge: src flat index == global dst id == i
        int j = (e < cnt) ? (b*NN + g_nbr[i*KK + e]) : i;
        float rx = g_posx[j] - cx, ry = g_posy[j] - cy, rz = g_posz[j] - cz;
        float2 xw = ((const float2*)(g_xw + j*64))[lane];
        float h1a = fmaf(rz, w1z.x, fmaf(ry, w1y.x, fmaf(rx, w1x.x, xw.x)));
        float h1b = fmaf(rz, w1z.y, fmaf(ry, w1y.y, fmaf(rx, w1x.y, xw.y)));
        h1a = fmaxf(h1a, 0.0f);
        h1b = fmaxf(h1b, 0.0f);

        float a0 = bb2.x, a1 = bb2.y;
        #pragma unroll 8
        for (int k0 = 0; k0 < 32; k0++) {
            float va = __shfl_sync(0xffffffffu, h1a, k0);   // h1[2*k0]
            float vb = __shfl_sync(0xffffffffu, h1b, k0);   // h1[2*k0+1]
            float2 wa = ((const float2*)(W2s + (2*k0  )*64))[lane];
            float2 wb = ((const float2*)(W2s + (2*k0+1)*64))[lane];
            a0 = fmaf(va, wa.x, a0); a0 = fmaf(vb, wb.x, a0);
            a1 = fmaf(va, wa.y, a1); a1 = fmaf(vb, wb.y, a1);
        }
        float h2a = fmaxf(a0, 0.0f), h2b = fmaxf(a1, 0.0f);

        float c0 = bb3.x, c1 = bb3.y, c2 = bb3.z, c3 = bb3.w;
        #pragma unroll 8
        for (int k0 = 0; k0 < 32; k0++) {
            float va = __shfl_sync(0xffffffffu, h2a, k0);   // h2[2*k0]
            float vb = __shfl_sync(0xffffffffu, h2b, k0);   // h2[2*k0+1]
            float4 wa = ((const float4*)(W3s + (2*k0  )*128))[lane];
            float4 wb = ((const float4*)(W3s + (2*k0+1)*128))[lane];
            c0 = fmaf(va, wa.x, c0); c0 = fmaf(vb, wb.x, c0);
            c1 = fmaf(va, wa.y, c1); c1 = fmaf(vb, wb.y, c1);
            c2 = fmaf(va, wa.z, c2); c2 = fmaf(vb, wb.z, c2);
            c3 = fmaf(va, wa.w, c3); c3 = fmaf(vb, wb.w, c3);
        }
        m0 = fmaxf(m0, c0); m1 = fmaxf(m1, c1);
        m2 = fmaxf(m2, c2); m3 = fmaxf(m3, c3);
    }
    ((float4*)(out_x + i*128))[lane] = make_float4(m0, m1, m2, m3);
}

// ---------------- host launcher ----------------
extern "C" void kernel_launch(void* const* d_in, const int* in_sizes, int n_in,
                              void* d_out, int out_size) {
    const float* x   = (const float*)d_in[0];
    const float* pos = (const float*)d_in[1];
    // d_in[2] = batch (int32) -- derivable, unused
    const float* W1  = (const float*)d_in[3];
    const float* b1  = (const float*)d_in[4];
    const float* W2  = (const float*)d_in[5];
    const float* b2  = (const float*)d_in[6];
    const float* W3  = (const float*)d_in[7];
    const float* b3  = (const float*)d_in[8];

    float* out   = (float*)d_out;
    float* out_c = (out_size >= MTOT*131) ? out + MTOT*128 : nullptr;
    float* out_b = (out_size >= MTOT*132) ? out + MTOT*131 : nullptr;

    cudaFuncSetAttribute(fps_grid_kernel, cudaFuncAttributeMaxDynamicSharedMemorySize, FPS2_SMEM);
    cudaFuncSetAttribute(mlp_kernel, cudaFuncAttributeMaxDynamicSharedMemorySize, MLP_SMEM);

    prep_kernel    <<<(BN + 255)/256, 256>>>(pos);
    count_kernel   <<<(BN + 255)/256, 256>>>();
    scan_kernel    <<<1, 32>>>();
    scatter_kernel <<<(BN + 255)/256, 256>>>();
    gather_kernel  <<<(BN + 255)/256, 256>>>();
    xw_kernel      <<<(BN*16 + 127)/128, 128>>>(x, W1, b1);
    fps_grid_kernel<<<BB, 1024, FPS2_SMEM>>>();
    centers_kernel <<<(MTOT + 255)/256, 256>>>(out_c, out_b);
    ballq_kernel   <<<MTOT/8, 256>>>();
    mlp_kernel     <<<MTOT/8, 256, MLP_SMEM>>>(W1, W2, b2, W3, b3, out);
}

// round 6
// speedup vs baseline: 1.3366x; 1.2251x over previous
#include <cuda_runtime.h>
#include <cstdint>

#define BB   2
#define NN   16384
#define SS   4096
#define KK   32
#define FIN  16
#define MTOT (BB*SS)      /* 8192 centers */
#define BN   (BB*NN)      /* 32768 points */
#define NCELL 1000        /* 10x10x10 cells of size R=0.1 per cloud */
#define R2   0.01f

// ---------------- device scratch (no runtime allocation allowed) ----------------
__device__ float g_posx[BN], g_posy[BN], g_posz[BN];
__device__ int   g_sidx[MTOT];                 // selected local point idx per (b,s)
__device__ float g_cx[MTOT], g_cy[MTOT], g_cz[MTOT];
__device__ int   g_cellCnt[BB*NCELL];
__device__ int   g_cellStart[BB*NCELL];
__device__ int   g_cellCur[BB*NCELL];
__device__ int   g_cellPts[BN];
__device__ float g_opx[BN], g_opy[BN], g_opz[BN];  // cell-ordered positions
__device__ int   g_opid[BN];                        // cell-ordered -> local point id
__device__ int2  g_ozp[BN];                         // fused {z bits, local pid}
__device__ float g_xw[BN*64];                  // x @ W1[:16] + b1   (8 MB)
__device__ int   g_nbr[MTOT*KK];
__device__ int   g_cnt[MTOT];

// ---------------- prep: SoA split of pos + zero cell counts ----------------
__global__ void prep_kernel(const float* __restrict__ pos) {
    int i = blockIdx.x * blockDim.x + threadIdx.x;
    if (i < BN) {
        g_posx[i] = pos[3*i+0];
        g_posy[i] = pos[3*i+1];
        g_posz[i] = pos[3*i+2];
    }
    if (i < BB*NCELL) g_cellCnt[i] = 0;
}

__device__ __forceinline__ int cell_of(float px, float py, float pz, int b) {
    int cx = (int)(px * 10.0f); cx = cx < 0 ? 0 : (cx > 9 ? 9 : cx);
    int cy = (int)(py * 10.0f); cy = cy < 0 ? 0 : (cy > 9 ? 9 : cy);
    int cz = (int)(pz * 10.0f); cz = cz < 0 ? 0 : (cz > 9 ? 9 : cz);
    return b * NCELL + (cz * 10 + cy) * 10 + cx;
}

__global__ void count_kernel() {
    int i = blockIdx.x * blockDim.x + threadIdx.x;
    if (i >= BN) return;
    int b = i >> 14;
    atomicAdd(&g_cellCnt[cell_of(g_posx[i], g_posy[i], g_posz[i], b)], 1);
}

// single-warp exclusive scan over 2000 cells
__global__ void scan_kernel() {
    int lane = threadIdx.x;
    int acc = 0;
    for (int base = 0; base < BB*NCELL; base += 32) {
        int idx = base + lane;
        int v = (idx < BB*NCELL) ? g_cellCnt[idx] : 0;
        int inc = v;
        #pragma unroll
        for (int o = 1; o < 32; o <<= 1) {
            int n = __shfl_up_sync(0xffffffffu, inc, o);
            if (lane >= o) inc += n;
        }
        if (idx < BB*NCELL) {
            g_cellStart[idx] = acc + inc - v;
            g_cellCur[idx]   = acc + inc - v;
        }
        acc += __shfl_sync(0xffffffffu, inc, 31);
    }
}

__global__ void scatter_kernel() {
    int i = blockIdx.x * blockDim.x + threadIdx.x;
    if (i >= BN) return;
    int b = i >> 14;
    int cid = cell_of(g_posx[i], g_posy[i], g_posz[i], b);
    int slot = atomicAdd(&g_cellCur[cid], 1);
    g_cellPts[slot] = i & (NN - 1);   // local index within cloud
}

// build cell-ordered SoA position arrays + id map
__global__ void gather_kernel() {
    int i = blockIdx.x * blockDim.x + threadIdx.x;
    if (i >= BN) return;
    int b = i >> 14;                 // slots of cloud b occupy [b*NN, (b+1)*NN)
    int pid = g_cellPts[i];
    int gp = b*NN + pid;
    float z = g_posz[gp];
    g_opx[i] = g_posx[gp];
    g_opy[i] = g_posy[gp];
    g_opz[i] = z;
    g_opid[i] = pid;
    g_ozp[i] = make_int2(__float_as_int(z), pid);
}

// ---------------- grid-pruned FPS, persistent lane-owns-cell ----------------
// key = (bits(dmin) << 32) | (0xFFFFFFFF - pid): max key == (max dmin, min pid)
__device__ __forceinline__ unsigned long long fps_key(float v, int pid) {
    return ((unsigned long long)__float_as_uint(v) << 32)
         | (unsigned long long)(0xFFFFFFFFu - (unsigned)pid);
}

#define FPS3_SMEM (3*NN*4 + 32*8 + 32*12 + 32)

__global__ void __launch_bounds__(1024, 1) fps_grid_kernel() {
    extern __shared__ float sm[];
    float* sx    = sm;                               // NN
    float* sy    = sx + NN;                          // NN
    float* sdmin = sy + NN;                          // NN
    unsigned long long* swk = (unsigned long long*)(sdmin + NN);  // 32 warp keys
    float* swx = (float*)(swk + 32);                 // 32
    float* swy = swx + 32;                           // 32
    float* swz = swy + 32;                           // 32
    float* slast = swz + 32;                         // 3

    const int b    = blockIdx.x;
    const int tid  = threadIdx.x;
    const int lane = tid & 31;
    const int wid  = tid >> 5;
    const int gbase = b * NN;

    for (int i = tid; i < NN; i += 1024) {
        sx[i] = g_opx[gbase + i];
        sy[i] = g_opy[gbase + i];
        sdmin[i] = 1e10f;
    }

    // lane-owned cell: c = (lane<<5) | wid
    const int mycell = (lane << 5) | wid;
    const bool valid = (mycell < NCELL);
    int cellStart = 0, cellCnt = 0;
    float cx0 = 0.f, cx1 = 0.f, cy0 = 0.f, cy1 = 0.f, cz0 = 0.f, cz1 = 0.f;
    unsigned long long cellKey = 0ull;
    float cellX = 0.f, cellY = 0.f, cellZ = 0.f;
    if (valid) {
        cellCnt   = g_cellCnt[b*NCELL + mycell];
        cellStart = g_cellStart[b*NCELL + mycell] - gbase;
        int cz = mycell / 100;
        int r  = mycell - cz * 100;
        int cy = r / 10;
        int cxi = r - cy * 10;
        cx0 = (float)cxi * 0.1f; cx1 = (float)(cxi+1) * 0.1f;
        cy0 = (float)cy  * 0.1f; cy1 = (float)(cy +1) * 0.1f;
        cz0 = (float)cz  * 0.1f; cz1 = (float)(cz +1) * 0.1f;
        cellKey = cellCnt ? fps_key(1e10f, 0) : 0ull;
    }
    if (tid == 0) {
        g_sidx[b*SS] = 0;
        slast[0] = g_posx[gbase];   // original point 0 of this cloud
        slast[1] = g_posy[gbase];
        slast[2] = g_posz[gbase];
    }
    __syncthreads();

    for (int t = 1; t < SS; t++) {
        const float lx = slast[0], ly = slast[1], lz = slast[2];

        // ---- prune: one lane per owned cell ----
        bool need = false;
        if (valid && cellCnt) {
            float ex = fmaxf(fmaxf(cx0 - lx, lx - cx1), 0.0f);
            float ey = fmaxf(fmaxf(cy0 - ly, ly - cy1), 0.0f);
            float ez = fmaxf(fmaxf(cz0 - lz, lz - cz1), 0.0f);
            float lb2 = fmaf(ez, ez, fmaf(ey, ey, ex*ex));
            float gv = __uint_as_float((unsigned)(cellKey >> 32));
            need = (lb2 * 0.9998f < gv);   // conservative: never wrongly skip
        }
        unsigned mask = __ballot_sync(0xffffffffu, need);

        // ---- process touched cells, software-pipelined z loads ----
        int src = -1, st = 0, cn = 0;
        int2 zp = make_int2(0, 0);
        if (mask) {
            src = __ffs(mask) - 1; mask &= mask - 1;
            st = __shfl_sync(0xffffffffu, cellStart, src);
            cn = __shfl_sync(0xffffffffu, cellCnt,   src);
            if (lane < cn) zp = __ldg(&g_ozp[gbase + st + lane]);
        }
        while (src >= 0) {
            // prefetch next touched cell
            int nsrc = -1, nst = 0, ncn = 0;
            int2 nzp = make_int2(0, 0);
            if (mask) {
                nsrc = __ffs(mask) - 1; mask &= mask - 1;
                nst = __shfl_sync(0xffffffffu, cellStart, nsrc);
                ncn = __shfl_sync(0xffffffffu, cellCnt,   nsrc);
                if (lane < ncn) nzp = __ldg(&g_ozp[gbase + nst + lane]);
            }
            // process current cell
            unsigned long long bk = 0ull;
            float bx = 0.f, by = 0.f, bz = 0.f;
            if (lane < cn) {
                int s = st + lane;
                float px = sx[s], py = sy[s], pz = __int_as_float(zp.x);
                float dx = px - lx, dy = py - ly, dz = pz - lz;
                float d  = fmaf(dz, dz, fmaf(dy, dy, dx*dx));
                float nm = fminf(sdmin[s], d);
                sdmin[s] = nm;
                bk = fps_key(nm, zp.y);
                bx = px; by = py; bz = pz;
            }
            for (int p = lane + 32; p < cn; p += 32) {   // rare: cells with >32 pts
                int s = st + p;
                int2 zp2 = __ldg(&g_ozp[gbase + s]);
                float px = sx[s], py = sy[s], pz = __int_as_float(zp2.x);
                float dx = px - lx, dy = py - ly, dz = pz - lz;
                float d  = fmaf(dz, dz, fmaf(dy, dy, dx*dx));
                float nm = fminf(sdmin[s], d);
                sdmin[s] = nm;
                unsigned long long k = fps_key(nm, zp2.y);
                if (k > bk) { bk = k; bx = px; by = py; bz = pz; }
            }
            #pragma unroll
            for (int o = 16; o; o >>= 1) {
                unsigned long long ok = __shfl_down_sync(0xffffffffu, bk, o);
                float ox = __shfl_down_sync(0xffffffffu, bx, o);
                float oy = __shfl_down_sync(0xffffffffu, by, o);
                float oz = __shfl_down_sync(0xffffffffu, bz, o);
                if (ok > bk) { bk = ok; bx = ox; by = oy; bz = oz; }
            }
            bk = __shfl_sync(0xffffffffu, bk, 0);
            bx = __shfl_sync(0xffffffffu, bx, 0);
            by = __shfl_sync(0xffffffffu, by, 0);
            bz = __shfl_sync(0xffffffffu, bz, 0);
            if (lane == src) { cellKey = bk; cellX = bx; cellY = by; cellZ = bz; }
            src = nsrc; st = nst; cn = ncn; zp = nzp;
        }

        // ---- warp best over owned cells (coords ride along) ----
        unsigned long long wk = cellKey;
        float wx = cellX, wy = cellY, wz = cellZ;
        #pragma unroll
        for (int o = 16; o; o >>= 1) {
            unsigned long long ok = __shfl_down_sync(0xffffffffu, wk, o);
            float ox = __shfl_down_sync(0xffffffffu, wx, o);
            float oy = __shfl_down_sync(0xffffffffu, wy, o);
            float oz = __shfl_down_sync(0xffffffffu, wz, o);
            if (ok > wk) { wk = ok; wx = ox; wy = oy; wz = oz; }
        }
        if (lane == 0) { swk[wid] = wk; swx[wid] = wx; swy[wid] = wy; swz[wid] = wz; }
        __syncthreads();

        // ---- final reduce (warp 0) ----
        if (wid == 0) {
            unsigned long long fk = swk[lane];
            float fx = swx[lane], fy = swy[lane], fz = swz[lane];
            #pragma unroll
            for (int o = 16; o; o >>= 1) {
                unsigned long long ok = __shfl_down_sync(0xffffffffu, fk, o);
                float ox = __shfl_down_sync(0xffffffffu, fx, o);
                float oy = __shfl_down_sync(0xffffffffu, fy, o);
                float oz = __shfl_down_sync(0xffffffffu, fz, o);
                if (ok > fk) { fk = ok; fx = ox; fy = oy; fz = oz; }
            }
            if (lane == 0) {
                int pid = (int)(0xFFFFFFFFu - (unsigned)(fk & 0xFFFFFFFFull));
                g_sidx[b*SS + t] = pid;
                slast[0] = fx; slast[1] = fy; slast[2] = fz;
            }
        }
        __syncthreads();
    }
}

// ---------------- centers + batch outputs ----------------
__global__ void centers_kernel(float* out_c, float* out_b) {
    int i = blockIdx.x * blockDim.x + threadIdx.x;
    if (i >= MTOT) return;
    int b = i >> 12;
    int gp = b*NN + g_sidx[i];
    float cx = g_posx[gp], cy = g_posy[gp], cz = g_posz[gp];
    g_cx[i] = cx; g_cy[i] = cy; g_cz[i] = cz;
    if (out_c) { out_c[3*i+0] = cx; out_c[3*i+1] = cy; out_c[3*i+2] = cz; }
    if (out_b) { out_b[i] = (float)b; }
}

// ---------------- xw precompute: x @ W1[:16] + b1 ----------------
__global__ void xw_kernel(const float* __restrict__ x,
                          const float* __restrict__ W1,
                          const float* __restrict__ b1) {
    int gid = blockIdx.x * blockDim.x + threadIdx.x;
    if (gid >= BN * 16) return;
    int j  = gid >> 4;
    int c4 = (gid & 15) * 4;
    float a0 = b1[c4+0], a1 = b1[c4+1], a2 = b1[c4+2], a3 = b1[c4+3];
    const float* xr = x + j * FIN;
    #pragma unroll
    for (int k = 0; k < FIN; k++) {
        float xv = xr[k];
        const float* w = W1 + k*64 + c4;
        a0 = fmaf(xv, w[0], a0);
        a1 = fmaf(xv, w[1], a1);
        a2 = fmaf(xv, w[2], a2);
        a3 = fmaf(xv, w[3], a3);
    }
    float4* dst = (float4*)(g_xw + j*64 + c4);
    *dst = make_float4(a0, a1, a2, a3);
}

// ---------------- ball query: warp per center, grid cells, K smallest indices ----------------
__global__ void __launch_bounds__(256) ballq_kernel() {
    __shared__ int cand[8][256];
    __shared__ int scnt_s[8];
    int wid = threadIdx.x >> 5, lane = threadIdx.x & 31;
    int i = blockIdx.x * 8 + wid;
    int b = i >> 12, s = i & 4095;
    float cx = g_cx[i], cy = g_cy[i], cz = g_cz[i];
    if (lane == 0) scnt_s[wid] = 0;
    __syncwarp();

    int icx = (int)(cx * 10.0f); icx = icx < 0 ? 0 : (icx > 9 ? 9 : icx);
    int icy = (int)(cy * 10.0f); icy = icy < 0 ? 0 : (icy > 9 ? 9 : icy);
    int icz = (int)(cz * 10.0f); icz = icz < 0 ? 0 : (icz > 9 ? 9 : icz);
    int zlo = icz > 0 ? icz-1 : 0, zhi = icz < 9 ? icz+1 : 9;
    int ylo = icy > 0 ? icy-1 : 0, yhi = icy < 9 ? icy+1 : 9;
    int xlo = icx > 0 ? icx-1 : 0, xhi = icx < 9 ? icx+1 : 9;

    for (int zz = zlo; zz <= zhi; zz++)
    for (int yy = ylo; yy <= yhi; yy++)
    for (int xx = xlo; xx <= xhi; xx++) {
        int cid = b*NCELL + (zz*10 + yy)*10 + xx;
        int st = g_cellStart[cid];
        int en = st + g_cellCnt[cid];
        for (int idx = st + lane; idx < en; idx += 32) {
            float dx = g_opx[idx] - cx, dy = g_opy[idx] - cy, dz = g_opz[idx] - cz;
            float d2 = fmaf(dz, dz, fmaf(dy, dy, dx*dx));
            int pid = g_opid[idx];
            bool ok = (d2 <= R2) && !(b == 0 && pid == s);  // PyG remove_self_loops
            if (ok) {
                int p = atomicAdd(&scnt_s[wid], 1);
                if (p < 256) cand[wid][p] = pid;
            }
        }
    }
    __syncwarp();
    int m = scnt_s[wid]; if (m > 256) m = 256;
    int take = m < KK ? m : KK;
    // extract 'take' smallest indices (index order = reference sort order)
    for (int r = 0; r < take; r++) {
        int bestkey = 0x7FFFFFFF;
        for (int j = lane; j < m; j += 32) {
            int v = cand[wid][j];          // removed entries hold 0x7FFF (> any pid)
            int key = (v << 8) | j;
            bestkey = min(bestkey, key);
        }
        #pragma unroll
        for (int o = 16; o; o >>= 1)
            bestkey = min(bestkey, __shfl_down_sync(0xffffffffu, bestkey, o));
        bestkey = __shfl_sync(0xffffffffu, bestkey, 0);
        if (lane == 0) {
            g_nbr[i*KK + r] = bestkey >> 8;
            cand[wid][bestkey & 255] = 0x7FFF;
        }
        __syncwarp();
    }
    if (lane == 0) g_cnt[i] = take;
}

// ---------------- fused MLP + max-pool: warp per center ----------------
#define MLP_SMEM ((4096 + 8192 + 192 + 64 + 128) * 4)

__global__ void __launch_bounds__(256) mlp_kernel(const float* __restrict__ W1,
                                                  const float* __restrict__ W2,
                                                  const float* __restrict__ b2,
                                                  const float* __restrict__ W3,
                                                  const float* __restrict__ b3,
                                                  float* __restrict__ out_x) {
    extern __shared__ float sm[];
    float* W2s  = sm;            // 64x64
    float* W3s  = W2s + 4096;    // 64x128
    float* W1rs = W3s + 8192;    // rows 16..18 of W1 (rel weights), 3x64
    float* b2s  = W1rs + 192;
    float* b3s  = b2s + 64;
    int tid = threadIdx.x;
    for (int k = tid; k < 4096; k += 256) W2s[k] = W2[k];
    for (int k = tid; k < 8192; k += 256) W3s[k] = W3[k];
    if (tid < 192) W1rs[tid] = W1[FIN*64 + tid];
    if (tid < 64)  b2s[tid] = b2[tid];
    if (tid < 128) b3s[tid] = b3[tid];
    __syncthreads();

    int wid = tid >> 5, lane = tid & 31;
    int i = blockIdx.x * 8 + wid;
    int b = i >> 12;
    int cnt = g_cnt[i];
    float cx = g_cx[i], cy = g_cy[i], cz = g_cz[i];

    float2 w1x = ((const float2*)(W1rs +   0))[lane];
    float2 w1y = ((const float2*)(W1rs +  64))[lane];
    float2 w1z = ((const float2*)(W1rs + 128))[lane];
    float2 bb2 = ((const float2*)b2s)[lane];
    float4 bb3 = ((const float4*)b3s)[lane];

    float m0 = -1e30f, m1 = -1e30f, m2 = -1e30f, m3 = -1e30f;

    for (int e = 0; e <= cnt; e++) {
        // e == cnt -> PyG add_self_loops edge: src flat index == global dst id == i
        int j = (e < cnt) ? (b*NN + g_nbr[i*KK + e]) : i;
        float rx = g_posx[j] - cx, ry = g_posy[j] - cy, rz = g_posz[j] - cz;
        float2 xw = ((const float2*)(g_xw + j*64))[lane];
        float h1a = fmaf(rz, w1z.x, fmaf(ry, w1y.x, fmaf(rx, w1x.x, xw.x)));
        float h1b = fmaf(rz, w1z.y, fmaf(ry, w1y.y, fmaf(rx, w1x.y, xw.y)));
        h1a = fmaxf(h1a, 0.0f);
        h1b = fmaxf(h1b, 0.0f);

        float a0 = bb2.x, a1 = bb2.y;
        #pragma unroll 8
        for (int k0 = 0; k0 < 32; k0++) {
            float va = __shfl_sync(0xffffffffu, h1a, k0);   // h1[2*k0]
            float vb = __shfl_sync(0xffffffffu, h1b, k0);   // h1[2*k0+1]
            float2 wa = ((const float2*)(W2s + (2*k0  )*64))[lane];
            float2 wb = ((const float2*)(W2s + (2*k0+1)*64))[lane];
            a0 = fmaf(va, wa.x, a0); a0 = fmaf(vb, wb.x, a0);
            a1 = fmaf(va, wa.y, a1); a1 = fmaf(vb, wb.y, a1);
        }
        float h2a = fmaxf(a0, 0.0f), h2b = fmaxf(a1, 0.0f);

        float c0 = bb3.x, c1 = bb3.y, c2 = bb3.z, c3 = bb3.w;
        #pragma unroll 8
        for (int k0 = 0; k0 < 32; k0++) {
            float va = __shfl_sync(0xffffffffu, h2a, k0);   // h2[2*k0]
            float vb = __shfl_sync(0xffffffffu, h2b, k0);   // h2[2*k0+1]
            float4 wa = ((const float4*)(W3s + (2*k0  )*128))[lane];
            float4 wb = ((const float4*)(W3s + (2*k0+1)*128))[lane];
            c0 = fmaf(va, wa.x, c0); c0 = fmaf(vb, wb.x, c0);
            c1 = fmaf(va, wa.y, c1); c1 = fmaf(vb, wb.y, c1);
            c2 = fmaf(va, wa.z, c2); c2 = fmaf(vb, wb.z, c2);
            c3 = fmaf(va, wa.w, c3); c3 = fmaf(vb, wb.w, c3);
        }
        m0 = fmaxf(m0, c0); m1 = fmaxf(m1, c1);
        m2 = fmaxf(m2, c2); m3 = fmaxf(m3, c3);
    }
    ((float4*)(out_x + i*128))[lane] = make_float4(m0, m1, m2, m3);
}

// ---------------- host launcher ----------------
extern "C" void kernel_launch(void* const* d_in, const int* in_sizes, int n_in,
                              void* d_out, int out_size) {
    const float* x   = (const float*)d_in[0];
    const float* pos = (const float*)d_in[1];
    // d_in[2] = batch (int32) -- derivable, unused
    const float* W1  = (const float*)d_in[3];
    const float* b1  = (const float*)d_in[4];
    const float* W2  = (const float*)d_in[5];
    const float* b2  = (const float*)d_in[6];
    const float* W3  = (const float*)d_in[7];
    const float* b3  = (const float*)d_in[8];

    float* out   = (float*)d_out;
    float* out_c = (out_size >= MTOT*131) ? out + MTOT*128 : nullptr;
    float* out_b = (out_size >= MTOT*132) ? out + MTOT*131 : nullptr;

    cudaFuncSetAttribute(fps_grid_kernel, cudaFuncAttributeMaxDynamicSharedMemorySize, FPS3_SMEM);
    cudaFuncSetAttribute(mlp_kernel, cudaFuncAttributeMaxDynamicSharedMemorySize, MLP_SMEM);

    prep_kernel    <<<(BN + 255)/256, 256>>>(pos);
    count_kernel   <<<(BN + 255)/256, 256>>>();
    scan_kernel    <<<1, 32>>>();
    scatter_kernel <<<(BN + 255)/256, 256>>>();
    gather_kernel  <<<(BN + 255)/256, 256>>>();
    xw_kernel      <<<(BN*16 + 127)/128, 128>>>(x, W1, b1);
    fps_grid_kernel<<<BB, 1024, FPS3_SMEM>>>();
    centers_kernel <<<(MTOT + 255)/256, 256>>>(out_c, out_b);
    ballq_kernel   <<<MTOT/8, 256>>>();
    mlp_kernel     <<<MTOT/8, 256, MLP_SMEM>>>(W1, W2, b2, W3, b3, out);
}

// round 7
// speedup vs baseline: 1.8468x; 1.3817x over previous
#include <cuda_runtime.h>
#include <cstdint>

#define BB   2
#define NN   16384
#define SS   4096
#define KK   32
#define FIN  16
#define MTOT (BB*SS)      /* 8192 centers */
#define BN   (BB*NN)      /* 32768 points */
#define NCELL 1000        /* 10x10x10 cells of size R=0.1 per cloud */
#define R2   0.01f

// ---------------- device scratch (no runtime allocation allowed) ----------------
__device__ float  g_posx[BN], g_posy[BN], g_posz[BN];
__device__ int    g_sidx[MTOT];                 // selected local point idx per (b,s)
__device__ float  g_cx[MTOT], g_cy[MTOT], g_cz[MTOT];
__device__ int    g_cellCnt[BB*NCELL];
__device__ int    g_cellStart[BB*NCELL];
__device__ int    g_cellCur[BB*NCELL];
__device__ int    g_cellPts[BN];
__device__ float  g_opx[BN], g_opy[BN], g_opz[BN];  // cell-ordered positions
__device__ int    g_opid[BN];                        // cell-ordered -> local point id
__device__ float4 g_pts[BN];                         // fused {x, y, z, bits(pid)}
__device__ float  g_xw[BN*64];                  // x @ W1[:16] + b1   (8 MB)
__device__ int    g_nbr[MTOT*KK];
__device__ int    g_cnt[MTOT];

// ---------------- prep: SoA split of pos + zero cell counts ----------------
__global__ void prep_kernel(const float* __restrict__ pos) {
    int i = blockIdx.x * blockDim.x + threadIdx.x;
    if (i < BN) {
        g_posx[i] = pos[3*i+0];
        g_posy[i] = pos[3*i+1];
        g_posz[i] = pos[3*i+2];
    }
    if (i < BB*NCELL) g_cellCnt[i] = 0;
}

__device__ __forceinline__ int cell_of(float px, float py, float pz, int b) {
    int cx = (int)(px * 10.0f); cx = cx < 0 ? 0 : (cx > 9 ? 9 : cx);
    int cy = (int)(py * 10.0f); cy = cy < 0 ? 0 : (cy > 9 ? 9 : cy);
    int cz = (int)(pz * 10.0f); cz = cz < 0 ? 0 : (cz > 9 ? 9 : cz);
    return b * NCELL + (cz * 10 + cy) * 10 + cx;
}

__global__ void count_kernel() {
    int i = blockIdx.x * blockDim.x + threadIdx.x;
    if (i >= BN) return;
    int b = i >> 14;
    atomicAdd(&g_cellCnt[cell_of(g_posx[i], g_posy[i], g_posz[i], b)], 1);
}

// single-warp exclusive scan over 2000 cells
__global__ void scan_kernel() {
    int lane = threadIdx.x;
    int acc = 0;
    for (int base = 0; base < BB*NCELL; base += 32) {
        int idx = base + lane;
        int v = (idx < BB*NCELL) ? g_cellCnt[idx] : 0;
        int inc = v;
        #pragma unroll
        for (int o = 1; o < 32; o <<= 1) {
            int n = __shfl_up_sync(0xffffffffu, inc, o);
            if (lane >= o) inc += n;
        }
        if (idx < BB*NCELL) {
            g_cellStart[idx] = acc + inc - v;
            g_cellCur[idx]   = acc + inc - v;
        }
        acc += __shfl_sync(0xffffffffu, inc, 31);
    }
}

__global__ void scatter_kernel() {
    int i = blockIdx.x * blockDim.x + threadIdx.x;
    if (i >= BN) return;
    int b = i >> 14;
    int cid = cell_of(g_posx[i], g_posy[i], g_posz[i], b);
    int slot = atomicAdd(&g_cellCur[cid], 1);
    g_cellPts[slot] = i & (NN - 1);   // local index within cloud
}

// build cell-ordered arrays: SoA pos (ballq), fused float4 (FPS), id map
__global__ void gather_kernel() {
    int i = blockIdx.x * blockDim.x + threadIdx.x;
    if (i >= BN) return;
    int b = i >> 14;                 // slots of cloud b occupy [b*NN, (b+1)*NN)
    int pid = g_cellPts[i];
    int gp = b*NN + pid;
    float px = g_posx[gp], py = g_posy[gp], pz = g_posz[gp];
    g_opx[i] = px;
    g_opy[i] = py;
    g_opz[i] = pz;
    g_opid[i] = pid;
    g_pts[i] = make_float4(px, py, pz, __int_as_float(pid));
}

// ---------------- grid-pruned FPS, lane-owns-cell, REDUX reductions ----------------
// ordering: (dmin desc, pid asc) — dmin>=0 so float bits are u32-monotone.
#define FPS5_SMEM (NN*4 + 32*4*5 + 32)

__global__ void __launch_bounds__(1024, 1) fps_grid_kernel() {
    extern __shared__ float sm[];
    float*    sdmin = sm;                         // NN
    unsigned* swd   = (unsigned*)(sdmin + NN);    // 32 warp best dmin bits
    unsigned* swp   = swd + 32;                   // 32 warp best pid
    float*    swx   = (float*)(swp + 32);         // 32
    float*    swy   = swx + 32;
    float*    swz   = swy + 32;
    float*    slast = swz + 32;                   // 3

    const int b    = blockIdx.x;
    const int tid  = threadIdx.x;
    const int lane = tid & 31;
    const int wid  = tid >> 5;
    const int gbase = b * NN;

    for (int i = tid; i < NN; i += 1024) sdmin[i] = 1e10f;

    // lane-owned cell: c = (lane<<5) | wid  (spreads 3x3x3 neighborhoods across warps)
    const int mycell = (lane << 5) | wid;
    const bool valid = (mycell < NCELL);
    int cellStart = 0, cellCnt = 0;
    float cx0 = 0.f, cx1 = 0.f, cy0 = 0.f, cy1 = 0.f, cz0 = 0.f, cz1 = 0.f;
    unsigned cellD = 0u, cellP = 0x7FFFFFFFu;     // per-cell best (dmin bits, pid)
    float cellX = 0.f, cellY = 0.f, cellZ = 0.f;
    if (valid) {
        cellCnt   = g_cellCnt[b*NCELL + mycell];
        cellStart = g_cellStart[b*NCELL + mycell] - gbase;
        int cz = mycell / 100;
        int r  = mycell - cz * 100;
        int cy = r / 10;
        int cxi = r - cy * 10;
        cx0 = (float)cxi * 0.1f; cx1 = (float)(cxi+1) * 0.1f;
        cy0 = (float)cy  * 0.1f; cy1 = (float)(cy +1) * 0.1f;
        cz0 = (float)cz  * 0.1f; cz1 = (float)(cz +1) * 0.1f;
        if (cellCnt) { cellD = __float_as_uint(1e10f); cellP = 0u; }
    }
    if (tid == 0) {
        g_sidx[b*SS] = 0;
        slast[0] = g_posx[gbase];   // original point 0 of this cloud
        slast[1] = g_posy[gbase];
        slast[2] = g_posz[gbase];
    }
    __syncthreads();

    for (int t = 1; t < SS; t++) {
        const float lx = slast[0], ly = slast[1], lz = slast[2];

        // ---- prune: one lane per owned cell (pure ALU) ----
        bool need = false;
        if (valid && cellCnt) {
            float ex = fmaxf(fmaxf(cx0 - lx, lx - cx1), 0.0f);
            float ey = fmaxf(fmaxf(cy0 - ly, ly - cy1), 0.0f);
            float ez = fmaxf(fmaxf(cz0 - lz, lz - cz1), 0.0f);
            float lb2 = fmaf(ez, ez, fmaf(ey, ey, ex*ex));
            need = (lb2 * 0.9998f < __uint_as_float(cellD));   // never wrongly skip
        }
        unsigned mask = __ballot_sync(0xffffffffu, need);

        // ---- process touched cells, software-pipelined float4 loads ----
        int src = -1, st = 0, cn = 0;
        float4 pt = make_float4(0.f, 0.f, 0.f, 0.f);
        if (mask) {
            src = __ffs(mask) - 1; mask &= mask - 1;
            st = __shfl_sync(0xffffffffu, cellStart, src);
            cn = __shfl_sync(0xffffffffu, cellCnt,   src);
            if (lane < cn) pt = __ldg(&g_pts[gbase + st + lane]);
        }
        while (src >= 0) {
            // prefetch next touched cell
            int nsrc = -1, nst = 0, ncn = 0;
            float4 npt = make_float4(0.f, 0.f, 0.f, 0.f);
            if (mask) {
                nsrc = __ffs(mask) - 1; mask &= mask - 1;
                nst = __shfl_sync(0xffffffffu, cellStart, nsrc);
                ncn = __shfl_sync(0xffffffffu, cellCnt,   nsrc);
                if (lane < ncn) npt = __ldg(&g_pts[gbase + nst + lane]);
            }
            // per-lane best over this cell's points
            unsigned bd = 0u, bp = 0x7FFFFFFFu;
            float bx = 0.f, by = 0.f, bz = 0.f;
            if (lane < cn) {
                int s = st + lane;
                float dx = pt.x - lx, dy = pt.y - ly, dz = pt.z - lz;
                float d  = fmaf(dz, dz, fmaf(dy, dy, dx*dx));
                float nm = fminf(sdmin[s], d);
                sdmin[s] = nm;
                bd = __float_as_uint(nm);
                bp = (unsigned)__float_as_int(pt.w);
                bx = pt.x; by = pt.y; bz = pt.z;
            }
            for (int p = lane + 32; p < cn; p += 32) {   // rare: cells with >32 pts
                int s = st + p;
                float4 q = __ldg(&g_pts[gbase + s]);
                float dx = q.x - lx, dy = q.y - ly, dz = q.z - lz;
                float d  = fmaf(dz, dz, fmaf(dy, dy, dx*dx));
                float nm = fminf(sdmin[s], d);
                sdmin[s] = nm;
                unsigned db = __float_as_uint(nm);
                unsigned pp = (unsigned)__float_as_int(q.w);
                if (db > bd || (db == bd && pp < bp)) { bd = db; bp = pp; bx = q.x; by = q.y; bz = q.z; }
            }
            // cell argmax via REDUX: max dmin bits, then min pid among matches
            unsigned mb = __reduce_max_sync(0xffffffffu, bd);
            unsigned cand = (bd == mb) ? bp : 0xFFFFFFFFu;
            unsigned mp = __reduce_min_sync(0xffffffffu, cand);
            unsigned wm = __ballot_sync(0xffffffffu, cand == mp);
            int wl = __ffs(wm) - 1;
            float wx = __shfl_sync(0xffffffffu, bx, wl);
            float wy = __shfl_sync(0xffffffffu, by, wl);
            float wz = __shfl_sync(0xffffffffu, bz, wl);
            if (lane == src) { cellD = mb; cellP = mp; cellX = wx; cellY = wy; cellZ = wz; }
            src = nsrc; st = nst; cn = ncn; pt = npt;
        }

        // ---- warp best over owned cells: REDUX + winner lane writes slot directly ----
        unsigned mb = __reduce_max_sync(0xffffffffu, cellD);
        unsigned cand = (cellD == mb) ? cellP : 0xFFFFFFFFu;
        unsigned mp = __reduce_min_sync(0xffffffffu, cand);
        unsigned wm = __ballot_sync(0xffffffffu, cand == mp);
        int wl = __ffs(wm) - 1;
        if (lane == wl) {
            swd[wid] = mb; swp[wid] = mp;
            swx[wid] = cellX; swy[wid] = cellY; swz[wid] = cellZ;
        }
        __syncthreads();

        // ---- final reduce (warp 0) ----
        if (wid == 0) {
            unsigned fd = swd[lane], fp = swp[lane];
            float fx = swx[lane], fy = swy[lane], fz = swz[lane];
            unsigned m2 = __reduce_max_sync(0xffffffffu, fd);
            unsigned c2 = (fd == m2) ? fp : 0xFFFFFFFFu;
            unsigned p2 = __reduce_min_sync(0xffffffffu, c2);
            unsigned w2 = __ballot_sync(0xffffffffu, c2 == p2);
            int wl2 = __ffs(w2) - 1;
            if (lane == wl2) {
                slast[0] = fx; slast[1] = fy; slast[2] = fz;
                g_sidx[b*SS + t] = (int)p2;
            }
        }
        __syncthreads();
    }
}

// ---------------- centers + batch outputs ----------------
__global__ void centers_kernel(float* out_c, float* out_b) {
    int i = blockIdx.x * blockDim.x + threadIdx.x;
    if (i >= MTOT) return;
    int b = i >> 12;
    int gp = b*NN + g_sidx[i];
    float cx = g_posx[gp], cy = g_posy[gp], cz = g_posz[gp];
    g_cx[i] = cx; g_cy[i] = cy; g_cz[i] = cz;
    if (out_c) { out_c[3*i+0] = cx; out_c[3*i+1] = cy; out_c[3*i+2] = cz; }
    if (out_b) { out_b[i] = (float)b; }
}

// ---------------- xw precompute: x @ W1[:16] + b1 ----------------
__global__ void xw_kernel(const float* __restrict__ x,
                          const float* __restrict__ W1,
                          const float* __restrict__ b1) {
    int gid = blockIdx.x * blockDim.x + threadIdx.x;
    if (gid >= BN * 16) return;
    int j  = gid >> 4;
    int c4 = (gid & 15) * 4;
    float a0 = b1[c4+0], a1 = b1[c4+1], a2 = b1[c4+2], a3 = b1[c4+3];
    const float* xr = x + j * FIN;
    #pragma unroll
    for (int k = 0; k < FIN; k++) {
        float xv = xr[k];
        const float* w = W1 + k*64 + c4;
        a0 = fmaf(xv, w[0], a0);
        a1 = fmaf(xv, w[1], a1);
        a2 = fmaf(xv, w[2], a2);
        a3 = fmaf(xv, w[3], a3);
    }
    float4* dst = (float4*)(g_xw + j*64 + c4);
    *dst = make_float4(a0, a1, a2, a3);
}

// ---------------- ball query: warp per center, grid cells, K smallest indices ----------------
__global__ void __launch_bounds__(256) ballq_kernel() {
    __shared__ int cand[8][256];
    __shared__ int scnt_s[8];
    int wid = threadIdx.x >> 5, lane = threadIdx.x & 31;
    int i = blockIdx.x * 8 + wid;
    int b = i >> 12, s = i & 4095;
    float cx = g_cx[i], cy = g_cy[i], cz = g_cz[i];
    if (lane == 0) scnt_s[wid] = 0;
    __syncwarp();

    int icx = (int)(cx * 10.0f); icx = icx < 0 ? 0 : (icx > 9 ? 9 : icx);
    int icy = (int)(cy * 10.0f); icy = icy < 0 ? 0 : (icy > 9 ? 9 : icy);
    int icz = (int)(cz * 10.0f); icz = icz < 0 ? 0 : (icz > 9 ? 9 : icz);
    int zlo = icz > 0 ? icz-1 : 0, zhi = icz < 9 ? icz+1 : 9;
    int ylo = icy > 0 ? icy-1 : 0, yhi = icy < 9 ? icy+1 : 9;
    int xlo = icx > 0 ? icx-1 : 0, xhi = icx < 9 ? icx+1 : 9;

    for (int zz = zlo; zz <= zhi; zz++)
    for (int yy = ylo; yy <= yhi; yy++)
    for (int xx = xlo; xx <= xhi; xx++) {
        int cid = b*NCELL + (zz*10 + yy)*10 + xx;
        int st = g_cellStart[cid];
        int en = st + g_cellCnt[cid];
        for (int idx = st + lane; idx < en; idx += 32) {
            float dx = g_opx[idx] - cx, dy = g_opy[idx] - cy, dz = g_opz[idx] - cz;
            float d2 = fmaf(dz, dz, fmaf(dy, dy, dx*dx));
            int pid = g_opid[idx];
            bool ok = (d2 <= R2) && !(b == 0 && pid == s);  // PyG remove_self_loops
            if (ok) {
                int p = atomicAdd(&scnt_s[wid], 1);
                if (p < 256) cand[wid][p] = pid;
            }
        }
    }
    __syncwarp();
    int m = scnt_s[wid]; if (m > 256) m = 256;
    int take = m < KK ? m : KK;
    // extract 'take' smallest indices (index order = reference sort order)
    for (int r = 0; r < take; r++) {
        int bestkey = 0x7FFFFFFF;
        for (int j = lane; j < m; j += 32) {
            int v = cand[wid][j];          // removed entries hold 0x7FFF (> any pid)
            int key = (v << 8) | j;
            bestkey = min(bestkey, key);
        }
        #pragma unroll
        for (int o = 16; o; o >>= 1)
            bestkey = min(bestkey, __shfl_down_sync(0xffffffffu, bestkey, o));
        bestkey = __shfl_sync(0xffffffffu, bestkey, 0);
        if (lane == 0) {
            g_nbr[i*KK + r] = bestkey >> 8;
            cand[wid][bestkey & 255] = 0x7FFF;
        }
        __syncwarp();
    }
    if (lane == 0) g_cnt[i] = take;
}

// ---------------- fused MLP + max-pool: warp per center ----------------
#define MLP_SMEM ((4096 + 8192 + 192 + 64 + 128) * 4)

__global__ void __launch_bounds__(256) mlp_kernel(const float* __restrict__ W1,
                                                  const float* __restrict__ W2,
                                                  const float* __restrict__ b2,
                                                  const float* __restrict__ W3,
                                                  const float* __restrict__ b3,
                                                  float* __restrict__ out_x) {
    extern __shared__ float sm[];
    float* W2s  = sm;            // 64x64
    float* W3s  = W2s + 4096;    // 64x128
    float* W1rs = W3s + 8192;    // rows 16..18 of W1 (rel weights), 3x64
    float* b2s  = W1rs + 192;
    float* b3s  = b2s + 64;
    int tid = threadIdx.x;
    for (int k = tid; k < 4096; k += 256) W2s[k] = W2[k];
    for (int k = tid; k < 8192; k += 256) W3s[k] = W3[k];
    if (tid < 192) W1rs[tid] = W1[FIN*64 + tid];
    if (tid < 64)  b2s[tid] = b2[tid];
    if (tid < 128) b3s[tid] = b3[tid];
    __syncthreads();

    int wid = tid >> 5, lane = tid & 31;
    int i = blockIdx.x * 8 + wid;
    int b = i >> 12;
    int cnt = g_cnt[i];
    float cx = g_cx[i], cy = g_cy[i], cz = g_cz[i];

    float2 w1x = ((const float2*)(W1rs +   0))[lane];
    float2 w1y = ((const float2*)(W1rs +  64))[lane];
    float2 w1z = ((const float2*)(W1rs + 128))[lane];
    float2 bb2 = ((const float2*)b2s)[lane];
    float4 bb3 = ((const float4*)b3s)[lane];

    float m0 = -1e30f, m1 = -1e30f, m2 = -1e30f, m3 = -1e30f;

    for (int e = 0; e <= cnt; e++) {
        // e == cnt -> PyG add_self_loops edge: src flat index == global dst id == i
        int j = (e < cnt) ? (b*NN + g_nbr[i*KK + e]) : i;
        float rx = g_posx[j] - cx, ry = g_posy[j] - cy, rz = g_posz[j] - cz;
        float2 xw = ((const float2*)(g_xw + j*64))[lane];
        float h1a = fmaf(rz, w1z.x, fmaf(ry, w1y.x, fmaf(rx, w1x.x, xw.x)));
        float h1b = fmaf(rz, w1z.y, fmaf(ry, w1y.y, fmaf(rx, w1x.y, xw.y)));
        h1a = fmaxf(h1a, 0.0f);
        h1b = fmaxf(h1b, 0.0f);

        float a0 = bb2.x, a1 = bb2.y;
        #pragma unroll 8
        for (int k0 = 0; k0 < 32; k0++) {
            float va = __shfl_sync(0xffffffffu, h1a, k0);   // h1[2*k0]
            float vb = __shfl_sync(0xffffffffu, h1b, k0);   // h1[2*k0+1]
            float2 wa = ((const float2*)(W2s + (2*k0  )*64))[lane];
            float2 wb = ((const float2*)(W2s + (2*k0+1)*64))[lane];
            a0 = fmaf(va, wa.x, a0); a0 = fmaf(vb, wb.x, a0);
            a1 = fmaf(va, wa.y, a1); a1 = fmaf(vb, wb.y, a1);
        }
        float h2a = fmaxf(a0, 0.0f), h2b = fmaxf(a1, 0.0f);

        float c0 = bb3.x, c1 = bb3.y, c2 = bb3.z, c3 = bb3.w;
        #pragma unroll 8
        for (int k0 = 0; k0 < 32; k0++) {
            float va = __shfl_sync(0xffffffffu, h2a, k0);   // h2[2*k0]
            float vb = __shfl_sync(0xffffffffu, h2b, k0);   // h2[2*k0+1]
            float4 wa = ((const float4*)(W3s + (2*k0  )*128))[lane];
            float4 wb = ((const float4*)(W3s + (2*k0+1)*128))[lane];
            c0 = fmaf(va, wa.x, c0); c0 = fmaf(vb, wb.x, c0);
            c1 = fmaf(va, wa.y, c1); c1 = fmaf(vb, wb.y, c1);
            c2 = fmaf(va, wa.z, c2); c2 = fmaf(vb, wb.z, c2);
            c3 = fmaf(va, wa.w, c3); c3 = fmaf(vb, wb.w, c3);
        }
        m0 = fmaxf(m0, c0); m1 = fmaxf(m1, c1);
        m2 = fmaxf(m2, c2); m3 = fmaxf(m3, c3);
    }
    ((float4*)(out_x + i*128))[lane] = make_float4(m0, m1, m2, m3);
}

// ---------------- host launcher ----------------
extern "C" void kernel_launch(void* const* d_in, const int* in_sizes, int n_in,
                              void* d_out, int out_size) {
    const float* x   = (const float*)d_in[0];
    const float* pos = (const float*)d_in[1];
    // d_in[2] = batch (int32) -- derivable, unused
    const float* W1  = (const float*)d_in[3];
    const float* b1  = (const float*)d_in[4];
    const float* W2  = (const float*)d_in[5];
    const float* b2  = (const float*)d_in[6];
    const float* W3  = (const float*)d_in[7];
    const float* b3  = (const float*)d_in[8];

    float* out   = (float*)d_out;
    float* out_c = (out_size >= MTOT*131) ? out + MTOT*128 : nullptr;
    float* out_b = (out_size >= MTOT*132) ? out + MTOT*131 : nullptr;

    cudaFuncSetAttribute(fps_grid_kernel, cudaFuncAttributeMaxDynamicSharedMemorySize, FPS5_SMEM);
    cudaFuncSetAttribute(mlp_kernel, cudaFuncAttributeMaxDynamicSharedMemorySize, MLP_SMEM);

    prep_kernel    <<<(BN + 255)/256, 256>>>(pos);
    count_kernel   <<<(BN + 255)/256, 256>>>();
    scan_kernel    <<<1, 32>>>();
    scatter_kernel <<<(BN + 255)/256, 256>>>();
    gather_kernel  <<<(BN + 255)/256, 256>>>();
    xw_kernel      <<<(BN*16 + 127)/128, 128>>>(x, W1, b1);
    fps_grid_kernel<<<BB, 1024, FPS5_SMEM>>>();
    centers_kernel <<<(MTOT + 255)/256, 256>>>(out_c, out_b);
    ballq_kernel   <<<MTOT/8, 256>>>();
    mlp_kernel     <<<MTOT/8, 256, MLP_SMEM>>>(W1, W2, b2, W3, b3, out);
}